// round 2
// baseline (speedup 1.0000x reference)
#include <cuda_runtime.h>
#include <math.h>

#define NN 50000
#define NE 800000
#define NG 64
#define FI 128
#define FH 192
#define FO 128
#define NC 10

// ---------------- device scratch (static allocation; no cudaMalloc) ----------------
__device__ int   g_deg[NN];
__device__ int   g_fill[NN];
__device__ float g_dis[NN];
__device__ int   g_rowptr[NN + 1];
__device__ int   g_colidx[NE];
__device__ float g_ew[NE];

__device__ float g_t1[(size_t)NN * FH];
__device__ float g_t2[(size_t)NN * FH];
__device__ float g_hA[(size_t)NN * FH];
__device__ float g_hB[(size_t)NN * FH];
__device__ float g_wcat[3 * FH * FH];       // max 576 x 192
__device__ float g_pool[NG * FO];
__device__ int   g_cnt[NG];

// ---------------- graph prep ----------------
__global__ void zero_kernel() {
    int i = blockIdx.x * blockDim.x + threadIdx.x;
    if (i < NN) { g_deg[i] = 0; g_fill[i] = 0; }
    if (i < NG * FO) g_pool[i] = 0.f;
    if (i < NG) g_cnt[i] = 0;
}

__global__ void hist_kernel(const int* __restrict__ ei) {
    int e = blockIdx.x * blockDim.x + threadIdx.x;
    if (e < NE) atomicAdd(&g_deg[ei[e]], 1);
}

__global__ void dis_kernel() {
    int i = blockIdx.x * blockDim.x + threadIdx.x;
    if (i < NN) {
        int d = g_deg[i];
        g_dis[i] = (d > 0) ? rsqrtf((float)d) : 0.f;
    }
}

// single-block exclusive scan of deg -> rowptr
__global__ void scan_kernel() {
    __shared__ int sh[1024];
    int tid = threadIdx.x;
    int offset = 0;
    for (int base = 0; base < NN; base += 1024) {
        int i = base + tid;
        int v = (i < NN) ? g_deg[i] : 0;
        sh[tid] = v;
        __syncthreads();
        for (int d = 1; d < 1024; d <<= 1) {
            int t = (tid >= d) ? sh[tid - d] : 0;
            __syncthreads();
            if (tid >= d) sh[tid] += t;
            __syncthreads();
        }
        if (i < NN) g_rowptr[i + 1] = offset + sh[tid];
        offset += sh[1023];
        __syncthreads();
    }
    if (tid == 0) g_rowptr[0] = 0;
}

__global__ void fill_kernel(const int* __restrict__ ei) {
    int e = blockIdx.x * blockDim.x + threadIdx.x;
    if (e >= NE) return;
    int r = ei[e];
    int c = ei[NE + e];
    int p = g_rowptr[r] + atomicAdd(&g_fill[r], 1);
    g_colidx[p] = c;
    g_ew[p] = -g_dis[r] * g_dis[c];     // scale = 2/lambda_max = 1, diag = 0
}

// ---------------- SpMM: hout[r,:] = sum_e w_e * hin[col_e,:]  (one warp per row) ----------------
template <int F>
__global__ void spmm_kernel(const float* __restrict__ hin, float* __restrict__ hout) {
    int gw = (int)((blockIdx.x * (size_t)blockDim.x + threadIdx.x) >> 5);
    int lane = threadIdx.x & 31;
    if (gw >= NN) return;
    int s = g_rowptr[gw];
    int e = g_rowptr[gw + 1];
    const int NV = F / 32;
    float acc[NV];
#pragma unroll
    for (int v = 0; v < NV; v++) acc[v] = 0.f;
    for (int i = s; i < e; i++) {
        int c = __ldg(&g_colidx[i]);
        float w = __ldg(&g_ew[i]);
        const float* hr = hin + (size_t)c * F;
#pragma unroll
        for (int v = 0; v < NV; v++) acc[v] = fmaf(w, __ldg(&hr[lane + 32 * v]), acc[v]);
    }
    float* o = hout + (size_t)gw * F;
#pragma unroll
    for (int v = 0; v < NV; v++) o[lane + 32 * v] = acc[v];
}

// ---------------- weight fold: wcat = [W0 - W2 ; W1 ; 2*W2] ----------------
__global__ void prep_wcat(const float* __restrict__ W, int finfo) {
    int i = blockIdx.x * blockDim.x + threadIdx.x;
    if (i >= finfo) return;
    float w0 = W[i], w1 = W[finfo + i], w2 = W[2 * finfo + i];
    g_wcat[i] = w0 - w2;
    g_wcat[finfo + i] = w1;
    g_wcat[2 * finfo + i] = 2.f * w2;
}

// ---------------- fused GEMM: out = [h|t1|t2] @ wcat + bias ----------------
#define BM 128
#define BN 64
#define BK 32

__global__ __launch_bounds__(256) void gemm_cheb(
    const float* __restrict__ h, const float* __restrict__ t1p, const float* __restrict__ t2p,
    const float* __restrict__ bias, float* __restrict__ out, int Fin, int Fo)
{
    __shared__ __align__(16) float As[BK][BM + 4];
    __shared__ __align__(16) float Bs[BK][BN];
    int tid = threadIdx.x;
    int tile_m = blockIdx.x * BM;
    int tile_n = blockIdx.y * BN;
    int K3 = 3 * Fin;
    const float* bufs[3] = { h, t1p, t2p };

    float acc[8][4];
#pragma unroll
    for (int i = 0; i < 8; i++)
#pragma unroll
        for (int j = 0; j < 4; j++) acc[i][j] = 0.f;

    int a_row = tid >> 3;           // 0..31
    int a_k4 = (tid & 7) << 2;      // 0,4,...,28
    int b_kr = tid >> 4;            // 0..15
    int b_c4 = (tid & 15) << 2;     // 0..60

    for (int k0 = 0; k0 < K3; k0 += BK) {
        const float* A = bufs[k0 / Fin];
        int kl = k0 % Fin;
#pragma unroll
        for (int r = 0; r < 4; r++) {
            int m = tile_m + a_row + r * 32;
            float4 v = make_float4(0.f, 0.f, 0.f, 0.f);
            if (m < NN) v = *reinterpret_cast<const float4*>(A + (size_t)m * Fin + kl + a_k4);
            As[a_k4 + 0][a_row + r * 32] = v.x;
            As[a_k4 + 1][a_row + r * 32] = v.y;
            As[a_k4 + 2][a_row + r * 32] = v.z;
            As[a_k4 + 3][a_row + r * 32] = v.w;
        }
#pragma unroll
        for (int r = 0; r < 2; r++) {
            int k = k0 + b_kr + r * 16;
            *reinterpret_cast<float4*>(&Bs[b_kr + r * 16][b_c4]) =
                *reinterpret_cast<const float4*>(&g_wcat[(size_t)k * Fo + tile_n + b_c4]);
        }
        __syncthreads();
        int tm = (tid >> 4) << 3;   // 0..120
        int tn = (tid & 15) << 2;   // 0..60
#pragma unroll
        for (int kk = 0; kk < BK; kk++) {
            float a[8], b[4];
            *reinterpret_cast<float4*>(&a[0]) = *reinterpret_cast<const float4*>(&As[kk][tm]);
            *reinterpret_cast<float4*>(&a[4]) = *reinterpret_cast<const float4*>(&As[kk][tm + 4]);
            *reinterpret_cast<float4*>(&b[0]) = *reinterpret_cast<const float4*>(&Bs[kk][tn]);
#pragma unroll
            for (int i = 0; i < 8; i++)
#pragma unroll
                for (int j = 0; j < 4; j++)
                    acc[i][j] = fmaf(a[i], b[j], acc[i][j]);
        }
        __syncthreads();
    }

    int tm = tile_m + ((tid >> 4) << 3);
    int tn = tile_n + ((tid & 15) << 2);
    float4 bb = *reinterpret_cast<const float4*>(&bias[tn]);
#pragma unroll
    for (int i = 0; i < 8; i++) {
        if (tm + i < NN) {
            float4 o = make_float4(acc[i][0] + bb.x, acc[i][1] + bb.y,
                                   acc[i][2] + bb.z, acc[i][3] + bb.w);
            *reinterpret_cast<float4*>(&out[(size_t)(tm + i) * Fo + tn]) = o;
        }
    }
}

// ---------------- global mean pool (batch is sorted) ----------------
__global__ void pool_kernel(const float* __restrict__ h, const int* __restrict__ batch) {
    int t = threadIdx.x;                 // 128 = F_OUT columns
    int base = blockIdx.x * 128;
    int cur = -1;
    float acc = 0.f;
    int cnt = 0;
    for (int n = 0; n < 128; n++) {
        int g = base + n;
        if (g >= NN) break;
        int bg = batch[g];
        if (bg != cur) {
            if (cur >= 0) {
                atomicAdd(&g_pool[cur * FO + t], acc);
                if (t == 0) atomicAdd(&g_cnt[cur], cnt);
            }
            cur = bg; acc = 0.f; cnt = 0;
        }
        acc += h[(size_t)g * FO + t];
        cnt++;
    }
    if (cur >= 0) {
        atomicAdd(&g_pool[cur * FO + t], acc);
        if (t == 0) atomicAdd(&g_cnt[cur], cnt);
    }
}

// ---------------- FC + log_softmax ----------------
__global__ void final_kernel(const float* __restrict__ fcw, const float* __restrict__ fcb,
                             float* __restrict__ out) {
    __shared__ float lg[NG][NC];
    __shared__ float smax[NG], slse[NG];
    int t = threadIdx.x;
    if (t < NG * NC) {
        int g = t / NC, c = t % NC;
        float inv = 1.f / fmaxf((float)g_cnt[g], 1.f);
        float s = fcb[c];
        for (int f = 0; f < FO; f++)
            s = fmaf(g_pool[g * FO + f] * inv, fcw[f * NC + c], s);
        lg[g][c] = s;
    }
    __syncthreads();
    if (t < NG) {
        float m = -1e30f;
        for (int c = 0; c < NC; c++) m = fmaxf(m, lg[t][c]);
        float se = 0.f;
        for (int c = 0; c < NC; c++) se += expf(lg[t][c] - m);
        smax[t] = m;
        slse[t] = logf(se);
    }
    __syncthreads();
    if (t < NG * NC) {
        int g = t / NC, c = t % NC;
        out[t] = lg[g][c] - smax[g] - slse[g];
    }
}

// ---------------- launch ----------------
extern "C" void kernel_launch(void* const* d_in, const int* in_sizes, int n_in,
                              void* d_out, int out_size) {
    const float* x   = (const float*)d_in[0];
    const int*   ei  = (const int*)d_in[1];
    const int*   bat = (const int*)d_in[2];
    const float* W1  = (const float*)d_in[3];
    const float* b1  = (const float*)d_in[4];
    const float* W2  = (const float*)d_in[5];
    const float* b2  = (const float*)d_in[6];
    const float* W3  = (const float*)d_in[7];
    const float* b3  = (const float*)d_in[8];
    const float* fcw = (const float*)d_in[9];
    const float* fcb = (const float*)d_in[10];
    float* out = (float*)d_out;

    float *t1, *t2, *hA, *hB;
    cudaGetSymbolAddress((void**)&t1, g_t1);
    cudaGetSymbolAddress((void**)&t2, g_t2);
    cudaGetSymbolAddress((void**)&hA, g_hA);
    cudaGetSymbolAddress((void**)&hB, g_hB);

    zero_kernel<<<(NN + 255) / 256, 256>>>();
    hist_kernel<<<(NE + 255) / 256, 256>>>(ei);
    dis_kernel<<<(NN + 255) / 256, 256>>>();
    scan_kernel<<<1, 1024>>>();
    fill_kernel<<<(NE + 255) / 256, 256>>>(ei);

    const int spmmBlocks = (NN * 32 + 255) / 256;
    dim3 gemmGridH((NN + BM - 1) / BM, FH / BN);   // Fo = 192
    dim3 gemmGridO((NN + BM - 1) / BM, FO / BN);   // Fo = 128

    // layer 1: Fin=128 -> Fo=192
    spmm_kernel<FI><<<spmmBlocks, 256>>>(x, t1);
    spmm_kernel<FI><<<spmmBlocks, 256>>>(t1, t2);
    prep_wcat<<<(FI * FH + 255) / 256, 256>>>(W1, FI * FH);
    gemm_cheb<<<gemmGridH, 256>>>(x, t1, t2, b1, hA, FI, FH);

    // layer 2: Fin=192 -> Fo=192
    spmm_kernel<FH><<<spmmBlocks, 256>>>(hA, t1);
    spmm_kernel<FH><<<spmmBlocks, 256>>>(t1, t2);
    prep_wcat<<<(FH * FH + 255) / 256, 256>>>(W2, FH * FH);
    gemm_cheb<<<gemmGridH, 256>>>(hA, t1, t2, b2, hB, FH, FH);

    // layer 3: Fin=192 -> Fo=128
    spmm_kernel<FH><<<spmmBlocks, 256>>>(hB, t1);
    spmm_kernel<FH><<<spmmBlocks, 256>>>(t1, t2);
    prep_wcat<<<(FH * FO + 255) / 256, 256>>>(W3, FH * FO);
    gemm_cheb<<<gemmGridO, 256>>>(hB, t1, t2, b3, hA, FH, FO);

    // pool + classifier
    pool_kernel<<<(NN + 127) / 128, 128>>>(hA, bat);
    final_kernel<<<1, 640>>>(fcw, fcb, out);
}

// round 3
// speedup vs baseline: 1.0161x; 1.0161x over previous
#include <cuda_runtime.h>
#include <math.h>

#define NN 50000
#define NE 800000
#define NG 64
#define FI 128
#define FH 192
#define FO 128
#define NC 10

// ---------------- device scratch ----------------
__device__ int   g_deg[NN];
__device__ int   g_fill[NN];
__device__ float g_dis[NN];
__device__ int   g_rowptr[NN + 1];
__device__ int   g_bsum[256];
__device__ int   g_boff[256];
__device__ int   g_colidx[NE];
__device__ float g_ew[NE];

__device__ float g_t1[(size_t)NN * FH];
__device__ float g_t2[(size_t)NN * FH];
__device__ float g_hA[(size_t)NN * FH];
__device__ float g_hB[(size_t)NN * FH];
__device__ float g_wcat[3 * FH * FH];
__device__ float g_pool[NG * FO];
__device__ int   g_cnt[NG];

// ---------------- graph prep ----------------
__global__ void zero_kernel() {
    int i = blockIdx.x * blockDim.x + threadIdx.x;
    if (i < NN) { g_deg[i] = 0; g_fill[i] = 0; }
    if (i < NG * FO) g_pool[i] = 0.f;
    if (i < NG) g_cnt[i] = 0;
}

__global__ void hist_kernel(const int* __restrict__ ei) {
    int e = blockIdx.x * blockDim.x + threadIdx.x;
    if (e < NE) atomicAdd(&g_deg[ei[e]], 1);
}

__global__ void dis_kernel() {
    int i = blockIdx.x * blockDim.x + threadIdx.x;
    if (i < NN) {
        int d = g_deg[i];
        g_dis[i] = (d > 0) ? rsqrtf((float)d) : 0.f;
    }
}

// hierarchical scan: per-block inclusive scans
__global__ void scan1_kernel() {
    __shared__ int ws[8];
    int t = threadIdx.x, b = blockIdx.x;
    int lane = t & 31, w = t >> 5;
    int i = b * 256 + t;
    int v = (i < NN) ? g_deg[i] : 0;
    int incl = v;
#pragma unroll
    for (int d = 1; d < 32; d <<= 1) {
        int n = __shfl_up_sync(0xffffffff, incl, d);
        if (lane >= d) incl += n;
    }
    if (lane == 31) ws[w] = incl;
    __syncthreads();
    if (w == 0 && lane < 8) {
        int s = ws[lane];
#pragma unroll
        for (int d = 1; d < 8; d <<= 1) {
            int n = __shfl_up_sync(0xff, s, d);
            if (lane >= d) s += n;
        }
        ws[lane] = s;
    }
    __syncthreads();
    int off = (w > 0) ? ws[w - 1] : 0;
    incl += off;
    if (i < NN) g_rowptr[i + 1] = incl;
    if (t == 255) g_bsum[b] = incl;
}

__global__ void scan2_kernel(int nblk) {
    __shared__ int ws[8];
    int t = threadIdx.x;
    int lane = t & 31, w = t >> 5;
    int v = (t < nblk) ? g_bsum[t] : 0;
    int incl = v;
#pragma unroll
    for (int d = 1; d < 32; d <<= 1) {
        int n = __shfl_up_sync(0xffffffff, incl, d);
        if (lane >= d) incl += n;
    }
    if (lane == 31) ws[w] = incl;
    __syncthreads();
    if (w == 0 && lane < 8) {
        int s = ws[lane];
#pragma unroll
        for (int d = 1; d < 8; d <<= 1) {
            int n = __shfl_up_sync(0xff, s, d);
            if (lane >= d) s += n;
        }
        ws[lane] = s;
    }
    __syncthreads();
    int off = (w > 0) ? ws[w - 1] : 0;
    g_boff[t] = incl + off - v;   // exclusive
    if (t == 0) g_rowptr[0] = 0;
}

__global__ void scan3_kernel() {
    int i = blockIdx.x * blockDim.x + threadIdx.x;
    if (i < NN) g_rowptr[i + 1] += g_boff[i >> 8];
}

__global__ void fill_kernel(const int* __restrict__ ei) {
    int e = blockIdx.x * blockDim.x + threadIdx.x;
    if (e >= NE) return;
    int r = ei[e];
    int c = ei[NE + e];
    int p = g_rowptr[r] + atomicAdd(&g_fill[r], 1);
    g_colidx[p] = c;
    g_ew[p] = -g_dis[r] * g_dis[c];
}

// ---------------- SpMM (one warp per row, vectorized) ----------------
template <int F>
__global__ void spmm_kernel(const float* __restrict__ hin, float* __restrict__ hout) {
    int gw = (int)((blockIdx.x * (size_t)blockDim.x + threadIdx.x) >> 5);
    int lane = threadIdx.x & 31;
    if (gw >= NN) return;
    int s = g_rowptr[gw];
    int e = g_rowptr[gw + 1];
    float4 acc4 = make_float4(0.f, 0.f, 0.f, 0.f);
    float2 acc2 = make_float2(0.f, 0.f);
    for (int i = s; i < e; i++) {
        int c = __ldg(&g_colidx[i]);
        float w = __ldg(&g_ew[i]);
        const float* hr = hin + (size_t)c * F;
        float4 v = __ldg(reinterpret_cast<const float4*>(hr) + lane);
        acc4.x = fmaf(w, v.x, acc4.x);
        acc4.y = fmaf(w, v.y, acc4.y);
        acc4.z = fmaf(w, v.z, acc4.z);
        acc4.w = fmaf(w, v.w, acc4.w);
        if (F == 192) {
            float2 u = __ldg(reinterpret_cast<const float2*>(hr + 128) + lane);
            acc2.x = fmaf(w, u.x, acc2.x);
            acc2.y = fmaf(w, u.y, acc2.y);
        }
    }
    float* o = hout + (size_t)gw * F;
    reinterpret_cast<float4*>(o)[lane] = acc4;
    if (F == 192) reinterpret_cast<float2*>(o + 128)[lane] = acc2;
}

// ---------------- weight fold ----------------
__global__ void prep_wcat(const float* __restrict__ W, int finfo) {
    int i = blockIdx.x * blockDim.x + threadIdx.x;
    if (i >= finfo) return;
    float w0 = W[i], w1 = W[finfo + i], w2 = W[2 * finfo + i];
    g_wcat[i] = w0 - w2;
    g_wcat[finfo + i] = w1;
    g_wcat[2 * finfo + i] = 2.f * w2;
}

// ---------------- TF32 tensor-core GEMM: out = [h|t1|t2] @ wcat + bias ----------------
// BM=128, BN=64, BK=32; 4 warps, warp tile 64x32; B split into hi+lo tf32.

__device__ __forceinline__ unsigned f2tf(float f) {
    unsigned u;
    asm("cvt.rna.tf32.f32 %0, %1;" : "=r"(u) : "f"(f));
    return u;
}

#define MMA_TF32(c, A_, B_) \
    asm volatile("mma.sync.aligned.m16n8k8.row.col.f32.tf32.tf32.f32 " \
                 "{%0,%1,%2,%3},{%4,%5,%6,%7},{%8,%9},{%0,%1,%2,%3};" \
                 : "+f"((c)[0]), "+f"((c)[1]), "+f"((c)[2]), "+f"((c)[3]) \
                 : "r"((A_)[0]), "r"((A_)[1]), "r"((A_)[2]), "r"((A_)[3]), \
                   "r"((B_)[0]), "r"((B_)[1]))

__global__ __launch_bounds__(128) void gemm_cheb(
    const float* __restrict__ h, const float* __restrict__ t1p, const float* __restrict__ t2p,
    const float* __restrict__ bias, float* __restrict__ out, int Fin, int Fo)
{
    __shared__ unsigned As[128 * 36];     // m-major, stride 36 (conflict-free frags)
    __shared__ unsigned BsH[32 * 72];     // k-major, stride 72
    __shared__ unsigned BsL[32 * 72];

    int tid = threadIdx.x;
    int lane = tid & 31;
    int warp = tid >> 5;
    int wm = warp >> 1;        // 0..1
    int wn = warp & 1;         // 0..1
    int tile_m = blockIdx.x * 128;
    int tile_n = blockIdx.y * 64;
    int K3 = 3 * Fin;
    const float* bufs[3] = { h, t1p, t2p };

    float acc[4][4][4];
#pragma unroll
    for (int a = 0; a < 4; a++)
#pragma unroll
        for (int b = 0; b < 4; b++)
#pragma unroll
            for (int c = 0; c < 4; c++) acc[a][b][c] = 0.f;

    for (int k0 = 0; k0 < K3; k0 += 32) {
        const float* A = bufs[k0 / Fin];
        int kl = k0 % Fin;
        // stage A: 128 rows x 32 k
#pragma unroll
        for (int j = 0; j < 8; j++) {
            int idx = j * 128 + tid;
            int m = idx >> 3, kq = idx & 7;
            int gm = tile_m + m;
            float4 v = make_float4(0.f, 0.f, 0.f, 0.f);
            if (gm < NN) v = *reinterpret_cast<const float4*>(A + (size_t)gm * Fin + kl + kq * 4);
            uint4 u = make_uint4(f2tf(v.x), f2tf(v.y), f2tf(v.z), f2tf(v.w));
            *reinterpret_cast<uint4*>(&As[m * 36 + kq * 4]) = u;
        }
        // stage B hi/lo: 32 k x 64 n
#pragma unroll
        for (int j = 0; j < 4; j++) {
            int idx = j * 128 + tid;
            int kr = idx >> 4, nq = idx & 15;
            float4 w = *reinterpret_cast<const float4*>(
                &g_wcat[(size_t)(k0 + kr) * Fo + tile_n + nq * 4]);
            unsigned hx = f2tf(w.x), hy = f2tf(w.y), hz = f2tf(w.z), hw = f2tf(w.w);
            uint4 lo = make_uint4(
                f2tf(w.x - __uint_as_float(hx)), f2tf(w.y - __uint_as_float(hy)),
                f2tf(w.z - __uint_as_float(hz)), f2tf(w.w - __uint_as_float(hw)));
            *reinterpret_cast<uint4*>(&BsH[kr * 72 + nq * 4]) = make_uint4(hx, hy, hz, hw);
            *reinterpret_cast<uint4*>(&BsL[kr * 72 + nq * 4]) = lo;
        }
        __syncthreads();

#pragma unroll
        for (int ks = 0; ks < 4; ks++) {
            int kk = ks * 8;
            unsigned a[4][4], bh[4][2], bl[4][2];
#pragma unroll
            for (int mt = 0; mt < 4; mt++) {
                int r = (wm * 64 + mt * 16 + (lane >> 2)) * 36 + kk + (lane & 3);
                a[mt][0] = As[r];
                a[mt][1] = As[r + 8 * 36];
                a[mt][2] = As[r + 4];
                a[mt][3] = As[r + 8 * 36 + 4];
            }
#pragma unroll
            for (int nt = 0; nt < 4; nt++) {
                int c = wn * 32 + nt * 8 + (lane >> 2);
                bh[nt][0] = BsH[(kk + (lane & 3)) * 72 + c];
                bh[nt][1] = BsH[(kk + 4 + (lane & 3)) * 72 + c];
                bl[nt][0] = BsL[(kk + (lane & 3)) * 72 + c];
                bl[nt][1] = BsL[(kk + 4 + (lane & 3)) * 72 + c];
            }
#pragma unroll
            for (int mt = 0; mt < 4; mt++)
#pragma unroll
                for (int nt = 0; nt < 4; nt++) {
                    MMA_TF32(acc[mt][nt], a[mt], bh[nt]);
                    MMA_TF32(acc[mt][nt], a[mt], bl[nt]);
                }
        }
        __syncthreads();
    }

    // epilogue
#pragma unroll
    for (int mt = 0; mt < 4; mt++) {
        int r0 = tile_m + wm * 64 + mt * 16 + (lane >> 2);
#pragma unroll
        for (int nt = 0; nt < 4; nt++) {
            int c0 = tile_n + wn * 32 + nt * 8 + 2 * (lane & 3);
            float2 bb = *reinterpret_cast<const float2*>(bias + c0);
            if (r0 < NN) {
                float2 o = make_float2(acc[mt][nt][0] + bb.x, acc[mt][nt][1] + bb.y);
                *reinterpret_cast<float2*>(out + (size_t)r0 * Fo + c0) = o;
            }
            if (r0 + 8 < NN) {
                float2 o = make_float2(acc[mt][nt][2] + bb.x, acc[mt][nt][3] + bb.y);
                *reinterpret_cast<float2*>(out + (size_t)(r0 + 8) * Fo + c0) = o;
            }
        }
    }
}

// ---------------- global mean pool ----------------
__global__ void pool_kernel(const float* __restrict__ h, const int* __restrict__ batch) {
    int t = threadIdx.x;
    int base = blockIdx.x * 128;
    int cur = -1;
    float acc = 0.f;
    int cnt = 0;
    for (int n = 0; n < 128; n++) {
        int g = base + n;
        if (g >= NN) break;
        int bg = batch[g];
        if (bg != cur) {
            if (cur >= 0) {
                atomicAdd(&g_pool[cur * FO + t], acc);
                if (t == 0) atomicAdd(&g_cnt[cur], cnt);
            }
            cur = bg; acc = 0.f; cnt = 0;
        }
        acc += h[(size_t)g * FO + t];
        cnt++;
    }
    if (cur >= 0) {
        atomicAdd(&g_pool[cur * FO + t], acc);
        if (t == 0) atomicAdd(&g_cnt[cur], cnt);
    }
}

// ---------------- FC + log_softmax ----------------
__global__ void final_kernel(const float* __restrict__ fcw, const float* __restrict__ fcb,
                             float* __restrict__ out) {
    __shared__ float lg[NG][NC];
    __shared__ float smax[NG], slse[NG];
    int t = threadIdx.x;
    if (t < NG * NC) {
        int g = t / NC, c = t % NC;
        float inv = 1.f / fmaxf((float)g_cnt[g], 1.f);
        float s = fcb[c];
        for (int f = 0; f < FO; f++)
            s = fmaf(g_pool[g * FO + f] * inv, fcw[f * NC + c], s);
        lg[g][c] = s;
    }
    __syncthreads();
    if (t < NG) {
        float m = -1e30f;
        for (int c = 0; c < NC; c++) m = fmaxf(m, lg[t][c]);
        float se = 0.f;
        for (int c = 0; c < NC; c++) se += expf(lg[t][c] - m);
        smax[t] = m;
        slse[t] = logf(se);
    }
    __syncthreads();
    if (t < NG * NC) {
        int g = t / NC, c = t % NC;
        out[t] = lg[g][c] - smax[g] - slse[g];
    }
}

// ---------------- launch ----------------
extern "C" void kernel_launch(void* const* d_in, const int* in_sizes, int n_in,
                              void* d_out, int out_size) {
    const float* x   = (const float*)d_in[0];
    const int*   ei  = (const int*)d_in[1];
    const int*   bat = (const int*)d_in[2];
    const float* W1  = (const float*)d_in[3];
    const float* b1  = (const float*)d_in[4];
    const float* W2  = (const float*)d_in[5];
    const float* b2  = (const float*)d_in[6];
    const float* W3  = (const float*)d_in[7];
    const float* b3  = (const float*)d_in[8];
    const float* fcw = (const float*)d_in[9];
    const float* fcb = (const float*)d_in[10];
    float* out = (float*)d_out;

    float *t1, *t2, *hA, *hB;
    cudaGetSymbolAddress((void**)&t1, g_t1);
    cudaGetSymbolAddress((void**)&t2, g_t2);
    cudaGetSymbolAddress((void**)&hA, g_hA);
    cudaGetSymbolAddress((void**)&hB, g_hB);

    const int NB = (NN + 255) / 256;   // 196

    zero_kernel<<<(NN + 255) / 256, 256>>>();
    hist_kernel<<<(NE + 255) / 256, 256>>>(ei);
    dis_kernel<<<(NN + 255) / 256, 256>>>();
    scan1_kernel<<<NB, 256>>>();
    scan2_kernel<<<1, 256>>>(NB);
    scan3_kernel<<<NB, 256>>>();
    fill_kernel<<<(NE + 255) / 256, 256>>>(ei);

    const int spmmBlocks = (NN * 32 + 255) / 256;
    dim3 gemmGridH((NN + 127) / 128, FH / 64);
    dim3 gemmGridO((NN + 127) / 128, FO / 64);

    // layer 1: Fin=128 -> Fo=192
    spmm_kernel<FI><<<spmmBlocks, 256>>>(x, t1);
    spmm_kernel<FI><<<spmmBlocks, 256>>>(t1, t2);
    prep_wcat<<<(FI * FH + 255) / 256, 256>>>(W1, FI * FH);
    gemm_cheb<<<gemmGridH, 128>>>(x, t1, t2, b1, hA, FI, FH);

    // layer 2: Fin=192 -> Fo=192
    spmm_kernel<FH><<<spmmBlocks, 256>>>(hA, t1);
    spmm_kernel<FH><<<spmmBlocks, 256>>>(t1, t2);
    prep_wcat<<<(FH * FH + 255) / 256, 256>>>(W2, FH * FH);
    gemm_cheb<<<gemmGridH, 128>>>(hA, t1, t2, b2, hB, FH, FH);

    // layer 3: Fin=192 -> Fo=128
    spmm_kernel<FH><<<spmmBlocks, 256>>>(hB, t1);
    spmm_kernel<FH><<<spmmBlocks, 256>>>(t1, t2);
    prep_wcat<<<(FH * FO + 255) / 256, 256>>>(W3, FH * FO);
    gemm_cheb<<<gemmGridO, 128>>>(hB, t1, t2, b3, hA, FH, FO);

    pool_kernel<<<(NN + 127) / 128, 128>>>(hA, bat);
    final_kernel<<<1, 640>>>(fcw, fcb, out);
}